// round 8
// baseline (speedup 1.0000x reference)
#include <cuda_runtime.h>
#include <cuda_bf16.h>
#include <math.h>
#include <stdint.h>

#define D_MODEL 1024
#define NHEADS  16
#define DH      64
#define SEQ     2048
#define BATCH   2
#define WIN     128
#define MROWS   (BATCH * SEQ)   // 4096

// ---------------- scratch (static device memory) ----------------
__device__ float g_q [MROWS * D_MODEL];
__device__ float g_k [MROWS * D_MODEL];
__device__ float g_v [MROWS * D_MODEL];

__device__ __nv_bfloat16 g_xh [MROWS * D_MODEL];
__device__ __nv_bfloat16 g_xl [MROWS * D_MODEL];
__device__ __nv_bfloat16 g_wh [4 * D_MODEL * D_MODEL];
__device__ __nv_bfloat16 g_wl [4 * D_MODEL * D_MODEL];
__device__ __nv_bfloat16 g_aoh[MROWS * D_MODEL];
__device__ __nv_bfloat16 g_aol[MROWS * D_MODEL];

// ---------------- PTX helpers ----------------
__device__ __forceinline__ uint32_t smem_u32(const void* p) {
    uint32_t a;
    asm("{ .reg .u64 t; cvta.to.shared.u64 t, %1; cvt.u32.u64 %0, t; }"
        : "=r"(a) : "l"(p));
    return a;
}
#define CPA16(dst, src) \
    asm volatile("cp.async.cg.shared.global [%0], [%1], 16;" :: "r"(dst), "l"(src))
#define CPA_COMMIT() asm volatile("cp.async.commit_group;" ::: "memory")
#define CPA_WAIT1()  asm volatile("cp.async.wait_group 1;" ::: "memory")
#define CPA_WAIT0()  asm volatile("cp.async.wait_group 0;" ::: "memory")

#define LDM4(r, addr) \
    asm volatile("ldmatrix.sync.aligned.m8n8.x4.shared.b16 {%0,%1,%2,%3}, [%4];" \
        : "=r"((r)[0]), "=r"((r)[1]), "=r"((r)[2]), "=r"((r)[3]) : "r"(addr))

#define LDM4T(r, addr) \
    asm volatile("ldmatrix.sync.aligned.m8n8.x4.trans.shared.b16 {%0,%1,%2,%3}, [%4];" \
        : "=r"((r)[0]), "=r"((r)[1]), "=r"((r)[2]), "=r"((r)[3]) : "r"(addr))

#define MMA16816(acc, a, b0, b1) \
    asm volatile("mma.sync.aligned.m16n8k16.row.col.f32.bf16.bf16.f32 " \
        "{%0,%1,%2,%3}, {%4,%5,%6,%7}, {%8,%9}, {%0,%1,%2,%3};" \
        : "+f"((acc)[0]), "+f"((acc)[1]), "+f"((acc)[2]), "+f"((acc)[3]) \
        : "r"((a)[0]), "r"((a)[1]), "r"((a)[2]), "r"((a)[3]), "r"(b0), "r"(b1))

__device__ __forceinline__ void split2(float x, float y, uint32_t& oh, uint32_t& ol) {
    __nv_bfloat16 hx = __float2bfloat16(x), hy = __float2bfloat16(y);
    __nv_bfloat162 th; th.x = hx; th.y = hy;
    __nv_bfloat162 tl;
    tl.x = __float2bfloat16(x - __bfloat162float(hx));
    tl.y = __float2bfloat16(y - __bfloat162float(hy));
    oh = *(uint32_t*)&th; ol = *(uint32_t*)&tl;
}

// ---------------------------------------------------------------------------
// fp32 -> bf16 hi/lo split, all inputs in one launch.
// ---------------------------------------------------------------------------
__global__ __launch_bounds__(256)
void conv_all(const float* __restrict__ x,
              const float* __restrict__ Wq, const float* __restrict__ Wk,
              const float* __restrict__ Wv, const float* __restrict__ Wo)
{
    int blk = blockIdx.x;
    const float* src;
    __nv_bfloat16 *hi, *lo;
    int i;
    if (blk < 4096) {
        src = x; hi = g_xh; lo = g_xl;
        i = blk * 256 + threadIdx.x;
    } else {
        int w  = (blk - 4096) >> 10;
        int bb = (blk - 4096) & 1023;
        src = (w == 0) ? Wq : (w == 1) ? Wk : (w == 2) ? Wv : Wo;
        hi = g_wh + (size_t)w * D_MODEL * D_MODEL;
        lo = g_wl + (size_t)w * D_MODEL * D_MODEL;
        i = bb * 256 + threadIdx.x;
    }

    float4 v = ((const float4*)src)[i];
    uint32_t h01, l01, h23, l23;
    split2(v.x, v.y, h01, l01);
    split2(v.z, v.w, h23, l23);
    ((uint32_t*)hi)[i * 2]     = h01;
    ((uint32_t*)hi)[i * 2 + 1] = h23;
    ((uint32_t*)lo)[i * 2]     = l01;
    ((uint32_t*)lo)[i * 2 + 1] = l23;
}

// ---------------------------------------------------------------------------
// mma.sync bf16-split GEMM: C = A*W^T + bias, 128x128 tile, 8 warps,
// K-chunks of 32, cp.async 3-stage, 1 sync/chunk, 2 CTAs/SM.
// R8: B-fragment double buffer across kk, LDSM-before-CPA ordering,
//     per-warp mi/kk rotation to break issue convoys.
// ---------------------------------------------------------------------------
#define TILE_B  8192
#define STAGE_B 32768
#define NSTAGE  3
#define SMEM_DYN (NSTAGE * STAGE_B + 1024)

__global__ __launch_bounds__(256, 2)
void gemm_tc(const float* __restrict__ b0, const float* __restrict__ b1,
             const float* __restrict__ b2, float* __restrict__ out_direct, int mode)
{
    extern __shared__ char dsm_raw[];
    char* sm = (char*)(((uintptr_t)dsm_raw + 1023) & ~(uintptr_t)1023);
    const uint32_t sb = smem_u32(sm);
    const int tid = threadIdx.x, wid = tid >> 5, lane = tid & 31;
    const int bn = blockIdx.x * 128, bm = blockIdx.y * 128, z = blockIdx.z;

    const __nv_bfloat16 *Ah, *Al, *Wh, *Wl;
    const float* bias;
    float* C;
    if (mode == 0) {
        Ah = g_xh; Al = g_xl;
        Wh = g_wh + (size_t)z * D_MODEL * D_MODEL;
        Wl = g_wl + (size_t)z * D_MODEL * D_MODEL;
        bias = (z == 0) ? b0 : ((z == 1) ? b1 : b2);
        C = (z == 0) ? g_q : ((z == 1) ? g_k : g_v);
    } else {
        Ah = g_aoh; Al = g_aol;
        Wh = g_wh + (size_t)3 * D_MODEL * D_MODEL;
        Wl = g_wl + (size_t)3 * D_MODEL * D_MODEL;
        bias = b0;
        C = out_direct;
    }

    const int r = tid >> 1;
    const int half = tid & 1;
    const __nv_bfloat16* srcs[4] = {
        Ah + (size_t)(bm + r) * D_MODEL + half * 16,
        Al + (size_t)(bm + r) * D_MODEL + half * 16,
        Wh + (size_t)(bn + r) * D_MODEL + half * 16,
        Wl + (size_t)(bn + r) * D_MODEL + half * 16 };
    uint32_t sts_off[2];
#pragma unroll
    for (int s = 0; s < 2; s++) {
        uint32_t u = (uint32_t)(half * 2 + s);
        sts_off[s] = (uint32_t)r * 64 + ((u ^ ((uint32_t)r & 3)) << 4);
    }

    const int wm = (wid & 1) * 64;
    const int wn = (wid >> 1) * 32;
    const int mrot = wid & 3;          // mi rotation
    const int krot = (wid >> 2) & 1;   // kk rotation

    float acc[4][4][4];
#pragma unroll
    for (int mi = 0; mi < 4; mi++)
#pragma unroll
        for (int nj = 0; nj < 4; nj++)
#pragma unroll
            for (int q = 0; q < 4; q++) acc[mi][nj][q] = 0.f;

    const uint32_t lrow = lane & 15;
    const uint32_t lsel = lane >> 4;

    // prologue: chunks 0 and 1 -> stages 0 and 1
#pragma unroll
    for (int pc = 0; pc < 2; pc++) {
        uint32_t stb = sb + (uint32_t)pc * STAGE_B;
#pragma unroll
        for (int t = 0; t < 4; t++)
#pragma unroll
            for (int s = 0; s < 2; s++)
                CPA16(stb + t * TILE_B + sts_off[s], srcs[t] + pc * 32 + s * 8);
        CPA_COMMIT();
    }

    int stage_c = 0;
    int stage_n = 2;
    for (int c = 0; c < 32; c++) {
        if (c == 31) { CPA_WAIT0(); } else { CPA_WAIT1(); }
        __syncthreads();

        const uint32_t stg = sb + (uint32_t)stage_c * STAGE_B;
        const int kk0 = krot, kk1 = krot ^ 1;

        // ---- B fragments for first kk (LDSM issued BEFORE cp.async burst) ----
        uint32_t bh0[2][4], bl0[2][4], bh1[2][4], bl1[2][4];
#pragma unroll
        for (int jp = 0; jp < 2; jp++) {
            uint32_t rw = (uint32_t)(wn + jp * 16) + lrow;
            uint32_t u  = ((uint32_t)kk0 * 2 + lsel) ^ (rw & 3);
            uint32_t ab = stg + rw * 64 + (u << 4);
            LDM4(bh0[jp], ab + 2 * TILE_B);
            LDM4(bl0[jp], ab + 3 * TILE_B);
        }

        // ---- prefetch chunk c+2 (LSU work shadows under LDSM/MMA) ----
        if (c + 2 < 32) {
            uint32_t stb = sb + (uint32_t)stage_n * STAGE_B;
#pragma unroll
            for (int t = 0; t < 4; t++)
#pragma unroll
                for (int s = 0; s < 2; s++)
                    CPA16(stb + t * TILE_B + sts_off[s], srcs[t] + (c + 2) * 32 + s * 8);
            CPA_COMMIT();
        }

        // ---- B fragments for second kk (latency hidden under kk0 MMAs) ----
#pragma unroll
        for (int jp = 0; jp < 2; jp++) {
            uint32_t rw = (uint32_t)(wn + jp * 16) + lrow;
            uint32_t u  = ((uint32_t)kk1 * 2 + lsel) ^ (rw & 3);
            uint32_t ab = stg + rw * 64 + (u << 4);
            LDM4(bh1[jp], ab + 2 * TILE_B);
            LDM4(bl1[jp], ab + 3 * TILE_B);
        }

#pragma unroll
        for (int kx = 0; kx < 2; kx++) {
            const int kk = kx ? kk1 : kk0;
            uint32_t (*bh)[4] = kx ? bh1 : bh0;
            uint32_t (*bl)[4] = kx ? bl1 : bl0;
#pragma unroll
            for (int mx = 0; mx < 4; mx++) {
                const int mi = (mx + mrot) & 3;
                uint32_t ra = (uint32_t)(wm + mi * 16) + lrow;
                uint32_t u  = ((uint32_t)kk * 2 + lsel) ^ (ra & 3);
                uint32_t aa = stg + ra * 64 + (u << 4);
                uint32_t ah[4], al[4];
                LDM4(ah, aa);
                LDM4(al, aa + TILE_B);
#pragma unroll
                for (int nj = 0; nj < 4; nj++) {
                    const int jp = nj >> 1, w = nj & 1;
                    MMA16816(acc[mi][nj], ah, bh[jp][w], bh[jp][w + 2]);
                    MMA16816(acc[mi][nj], ah, bl[jp][w], bl[jp][w + 2]);
                    MMA16816(acc[mi][nj], al, bh[jp][w], bh[jp][w + 2]);
                }
            }
        }
        stage_c = (stage_c == NSTAGE - 1) ? 0 : stage_c + 1;
        stage_n = (stage_n == NSTAGE - 1) ? 0 : stage_n + 1;
    }

#pragma unroll
    for (int mi = 0; mi < 4; mi++) {
        const int row = bm + wm + mi * 16 + (lane >> 2);
#pragma unroll
        for (int nj = 0; nj < 4; nj++) {
            const int col = bn + wn + nj * 8 + ((lane & 3) << 1);
            float2 o0 = { acc[mi][nj][0] + bias[col], acc[mi][nj][1] + bias[col + 1] };
            float2 o1 = { acc[mi][nj][2] + bias[col], acc[mi][nj][3] + bias[col + 1] };
            *(float2*)&C[(size_t)row * D_MODEL + col]       = o0;
            *(float2*)&C[(size_t)(row + 8) * D_MODEL + col] = o1;
        }
    }
}

// ---------------------------------------------------------------------------
// Tensor-core flash attention with fused RoPE (unchanged from round 7).
// ---------------------------------------------------------------------------
__device__ __forceinline__ void rope16(float* x1, float* x2, int s, int cb, float scale) {
#pragma unroll
    for (int i = 0; i < 16; i++) {
        float invf = exp2f(-(float)(cb + i) * (13.2877123795494f / 32.f));
        float ang = (float)s * invf;
        float sn, cs;
        sincosf(ang, &sn, &cs);
        float o1 = (x1[i] * cs - x2[i] * sn) * scale;
        float o2 = (x1[i] * sn + x2[i] * cs) * scale;
        x1[i] = o1; x2[i] = o2;
    }
}

__device__ __forceinline__ void store_hl(char* bh, char* bl, int row, int cb, const float* v) {
#pragma unroll
    for (int i = 0; i < 16; i += 2) {
        uint32_t off = (uint32_t)row * 128 + (uint32_t)(cb + i) * 2;
        off ^= ((uint32_t)row & 7) << 4;
        uint32_t oh, ol;
        split2(v[i], v[i + 1], oh, ol);
        *(uint32_t*)(bh + off) = oh;
        *(uint32_t*)(bl + off) = ol;
    }
}

__global__ __launch_bounds__(128)
void attn_tc()
{
    __shared__ __align__(16) char sdata[49152];
    char* sQH = sdata;          char* sQL = sdata + 8192;
    char* sKH = sdata + 16384;  char* sKL = sdata + 24576;
    char* sVH = sdata + 32768;  char* sVL = sdata + 40960;
    const uint32_t sb = smem_u32(sdata);

    const int tid = threadIdx.x, wid = tid >> 5, lane = tid & 31;
    const int q0 = blockIdx.x * 64, h = blockIdx.y, b = blockIdx.z;
    const float* Qg = g_q + (size_t)b * SEQ * D_MODEL + h * DH;
    const float* Kg = g_k + (size_t)b * SEQ * D_MODEL + h * DH;
    const float* Vg = g_v + (size_t)b * SEQ * D_MODEL + h * DH;

    const int lrw = tid >> 1;
    const int lch = (tid & 1) * 16;

    {
        const float* qp = Qg + (size_t)(q0 + lrw) * D_MODEL;
        float x1[16], x2[16];
#pragma unroll
        for (int i = 0; i < 16; i += 4) {
            *(float4*)(x1 + i) = *(const float4*)(qp + lch + i);
            *(float4*)(x2 + i) = *(const float4*)(qp + lch + 32 + i);
        }
        rope16(x1, x2, q0 + lrw, lch, 0.125f);
        store_hl(sQH, sQL, lrw, lch, x1);
        store_hl(sQH, sQL, lrw, lch + 32, x2);
    }

    const int wq = wid * 16;
    float m0 = -1e30f, m1 = -1e30f, l0 = 0.f, l1 = 0.f;
    float acc[8][4];
#pragma unroll
    for (int nb = 0; nb < 8; nb++)
#pragma unroll
        for (int q = 0; q < 4; q++) acc[nb][q] = 0.f;

    int kv0 = q0 - WIN; if (kv0 < 0) kv0 = 0;
    const int nk = q0 + 64 - kv0;

    const int qg0 = q0 + wq + (lane >> 2);
    const int qg1 = qg0 + 8;

    for (int kb = 0; kb < nk; kb += 64) {
        const int kbase = kv0 + kb;

        __syncthreads();
        {
            const float* kp = Kg + (size_t)(kbase + lrw) * D_MODEL;
            float x1[16], x2[16];
#pragma unroll
            for (int i = 0; i < 16; i += 4) {
                *(float4*)(x1 + i) = *(const float4*)(kp + lch + i);
                *(float4*)(x2 + i) = *(const float4*)(kp + lch + 32 + i);
            }
            rope16(x1, x2, kbase + lrw, lch, 1.0f);
            store_hl(sKH, sKL, lrw, lch, x1);
            store_hl(sKH, sKL, lrw, lch + 32, x2);

            const float* vp = Vg + (size_t)(kbase + lrw) * D_MODEL;
            const int vc = (tid & 1) * 32;
            float va[16], vb[16];
#pragma unroll
            for (int i = 0; i < 16; i += 4) {
                *(float4*)(va + i) = *(const float4*)(vp + vc + i);
                *(float4*)(vb + i) = *(const float4*)(vp + vc + 16 + i);
            }
            store_hl(sVH, sVL, lrw, vc, va);
            store_hl(sVH, sVL, lrw, vc + 16, vb);
        }
        __syncthreads();

        float S[8][4];
#pragma unroll
        for (int nb = 0; nb < 8; nb++)
#pragma unroll
            for (int q = 0; q < 4; q++) S[nb][q] = 0.f;

#pragma unroll
        for (int ks = 0; ks < 4; ks++) {
            const uint32_t acb  = (uint32_t)ks * 32 + ((uint32_t)(lane >> 4) << 4);
            const uint32_t arow = (uint32_t)wq + (lane & 15);
            const uint32_t aoff = arow * 128 + (acb ^ ((arow & 7) << 4));
            uint32_t ah[4], al[4];
            LDM4(ah, sb + aoff);
            LDM4(al, sb + 8192 + aoff);
#pragma unroll
            for (int nb2 = 0; nb2 < 4; nb2++) {
                const uint32_t brow = (uint32_t)nb2 * 16 + (lane & 15);
                const uint32_t boff = brow * 128 + (acb ^ ((brow & 7) << 4));
                uint32_t bh[4], bl[4];
                LDM4(bh, sb + 16384 + boff);
                LDM4(bl, sb + 24576 + boff);
#pragma unroll
                for (int w = 0; w < 2; w++) {
                    const int nb = nb2 * 2 + w;
                    MMA16816(S[nb], ah, bh[w], bh[w + 2]);
                    MMA16816(S[nb], ah, bl[w], bl[w + 2]);
                    MMA16816(S[nb], al, bh[w], bh[w + 2]);
                }
            }
        }

#pragma unroll
        for (int nb = 0; nb < 8; nb++) {
            const int kg = kbase + nb * 8 + ((lane & 3) << 1);
            if (kg     > qg0 || kg     < qg0 - WIN) S[nb][0] = -1e30f;
            if (kg + 1 > qg0 || kg + 1 < qg0 - WIN) S[nb][1] = -1e30f;
            if (kg     > qg1 || kg     < qg1 - WIN) S[nb][2] = -1e30f;
            if (kg + 1 > qg1 || kg + 1 < qg1 - WIN) S[nb][3] = -1e30f;
        }
        float mx0 = -1e30f, mx1 = -1e30f;
#pragma unroll
        for (int nb = 0; nb < 8; nb++) {
            mx0 = fmaxf(mx0, fmaxf(S[nb][0], S[nb][1]));
            mx1 = fmaxf(mx1, fmaxf(S[nb][2], S[nb][3]));
        }
        mx0 = fmaxf(mx0, __shfl_xor_sync(0xffffffffu, mx0, 1));
        mx0 = fmaxf(mx0, __shfl_xor_sync(0xffffffffu, mx0, 2));
        mx1 = fmaxf(mx1, __shfl_xor_sync(0xffffffffu, mx1, 1));
        mx1 = fmaxf(mx1, __shfl_xor_sync(0xffffffffu, mx1, 2));

        const float mn0 = fmaxf(m0, mx0), mn1 = fmaxf(m1, mx1);
        const float e0 = __expf(m0 - mn0), e1 = __expf(m1 - mn1);
        m0 = mn0; m1 = mn1;

        float s0 = 0.f, s1 = 0.f;
#pragma unroll
        for (int nb = 0; nb < 8; nb++) {
            S[nb][0] = __expf(S[nb][0] - m0); s0 += S[nb][0];
            S[nb][1] = __expf(S[nb][1] - m0); s0 += S[nb][1];
            S[nb][2] = __expf(S[nb][2] - m1); s1 += S[nb][2];
            S[nb][3] = __expf(S[nb][3] - m1); s1 += S[nb][3];
        }
        s0 += __shfl_xor_sync(0xffffffffu, s0, 1);
        s0 += __shfl_xor_sync(0xffffffffu, s0, 2);
        s1 += __shfl_xor_sync(0xffffffffu, s1, 1);
        s1 += __shfl_xor_sync(0xffffffffu, s1, 2);
        l0 = l0 * e0 + s0;
        l1 = l1 * e1 + s1;
#pragma unroll
        for (int nb = 0; nb < 8; nb++) {
            acc[nb][0] *= e0; acc[nb][1] *= e0;
            acc[nb][2] *= e1; acc[nb][3] *= e1;
        }

#pragma unroll
        for (int j = 0; j < 4; j++) {
            uint32_t pah[4], pal[4];
            split2(S[2 * j][0],     S[2 * j][1],     pah[0], pal[0]);
            split2(S[2 * j][2],     S[2 * j][3],     pah[1], pal[1]);
            split2(S[2 * j + 1][0], S[2 * j + 1][1], pah[2], pal[2]);
            split2(S[2 * j + 1][2], S[2 * j + 1][3], pah[3], pal[3]);

            const uint32_t vrow = (uint32_t)j * 16 + (lane & 15);
#pragma unroll
            for (int nb2 = 0; nb2 < 4; nb2++) {
                const uint32_t vcb = (uint32_t)nb2 * 32 + ((uint32_t)(lane >> 4) << 4);
                const uint32_t boff = vrow * 128 + (vcb ^ ((vrow & 7) << 4));
                uint32_t vh[4], vl[4];
                LDM4T(vh, sb + 32768 + boff);
                LDM4T(vl, sb + 40960 + boff);
#pragma unroll
                for (int w = 0; w < 2; w++) {
                    const int nb = nb2 * 2 + w;
                    MMA16816(acc[nb], pah, vh[2 * w], vh[2 * w + 1]);
                    MMA16816(acc[nb], pal, vh[2 * w], vh[2 * w + 1]);
                    MMA16816(acc[nb], pah, vl[2 * w], vl[2 * w + 1]);
                }
            }
        }
    }

    const float inv0 = 1.f / l0, inv1 = 1.f / l1;
#pragma unroll
    for (int nb = 0; nb < 8; nb++) {
        const int col = h * DH + nb * 8 + ((lane & 3) << 1);
        const size_t i0 = ((size_t)b * SEQ + qg0) * D_MODEL + col;
        const size_t i1 = ((size_t)b * SEQ + qg1) * D_MODEL + col;
        uint32_t oh, ol;
        split2(acc[nb][0] * inv0, acc[nb][1] * inv0, oh, ol);
        *(uint32_t*)(g_aoh + i0) = oh;
        *(uint32_t*)(g_aol + i0) = ol;
        split2(acc[nb][2] * inv1, acc[nb][3] * inv1, oh, ol);
        *(uint32_t*)(g_aoh + i1) = oh;
        *(uint32_t*)(g_aol + i1) = ol;
    }
}

// ---------------------------------------------------------------------------
extern "C" void kernel_launch(void* const* d_in, const int* in_sizes, int n_in,
                              void* d_out, int out_size)
{
    const float* x  = (const float*)d_in[0];
    const float* Wq = (const float*)d_in[1];
    const float* bq = (const float*)d_in[2];
    const float* Wk = (const float*)d_in[3];
    const float* bk = (const float*)d_in[4];
    const float* Wv = (const float*)d_in[5];
    const float* bv = (const float*)d_in[6];
    const float* Wo = (const float*)d_in[7];
    const float* bo = (const float*)d_in[8];
    float* out = (float*)d_out;

    cudaFuncSetAttribute(gemm_tc, cudaFuncAttributeMaxDynamicSharedMemorySize, SMEM_DYN);

    conv_all<<<8192, 256>>>(x, Wq, Wk, Wv, Wo);

    gemm_tc<<<dim3(8, 32, 3), 256, SMEM_DYN>>>(bq, bk, bv, nullptr, 0);

    dim3 agrid(SEQ / 64, NHEADS, BATCH);
    attn_tc<<<agrid, 128>>>();

    gemm_tc<<<dim3(8, 32, 1), 256, SMEM_DYN>>>(bo, nullptr, nullptr, out, 1);
}

// round 9
// speedup vs baseline: 2.0963x; 2.0963x over previous
#include <cuda_runtime.h>
#include <cuda_bf16.h>
#include <math.h>
#include <stdint.h>

#define D_MODEL 1024
#define NHEADS  16
#define DH      64
#define SEQ     2048
#define BATCH   2
#define WIN     128
#define MROWS   (BATCH * SEQ)   // 4096

// ---------------- scratch (static device memory) ----------------
__device__ float g_q [MROWS * D_MODEL];
__device__ float g_k [MROWS * D_MODEL];
__device__ float g_v [MROWS * D_MODEL];

__device__ __nv_bfloat16 g_xh [MROWS * D_MODEL];
__device__ __nv_bfloat16 g_xl [MROWS * D_MODEL];
__device__ __nv_bfloat16 g_wh [4 * D_MODEL * D_MODEL];
__device__ __nv_bfloat16 g_wl [4 * D_MODEL * D_MODEL];
__device__ __nv_bfloat16 g_aoh[MROWS * D_MODEL];
__device__ __nv_bfloat16 g_aol[MROWS * D_MODEL];

// ---------------- PTX helpers ----------------
__device__ __forceinline__ uint32_t smem_u32(const void* p) {
    uint32_t a;
    asm("{ .reg .u64 t; cvta.to.shared.u64 t, %1; cvt.u32.u64 %0, t; }"
        : "=r"(a) : "l"(p));
    return a;
}
#define CPA16(dst, src) \
    asm volatile("cp.async.cg.shared.global [%0], [%1], 16;" :: "r"(dst), "l"(src))
#define CPA_COMMIT() asm volatile("cp.async.commit_group;" ::: "memory")
#define CPA_WAIT1()  asm volatile("cp.async.wait_group 1;" ::: "memory")
#define CPA_WAIT0()  asm volatile("cp.async.wait_group 0;" ::: "memory")

#define LDM4(r, addr) \
    asm volatile("ldmatrix.sync.aligned.m8n8.x4.shared.b16 {%0,%1,%2,%3}, [%4];" \
        : "=r"((r)[0]), "=r"((r)[1]), "=r"((r)[2]), "=r"((r)[3]) : "r"(addr))

#define LDM4T(r, addr) \
    asm volatile("ldmatrix.sync.aligned.m8n8.x4.trans.shared.b16 {%0,%1,%2,%3}, [%4];" \
        : "=r"((r)[0]), "=r"((r)[1]), "=r"((r)[2]), "=r"((r)[3]) : "r"(addr))

#define MMA16816(acc, a, b0, b1) \
    asm volatile("mma.sync.aligned.m16n8k16.row.col.f32.bf16.bf16.f32 " \
        "{%0,%1,%2,%3}, {%4,%5,%6,%7}, {%8,%9}, {%0,%1,%2,%3};" \
        : "+f"((acc)[0]), "+f"((acc)[1]), "+f"((acc)[2]), "+f"((acc)[3]) \
        : "r"((a)[0]), "r"((a)[1]), "r"((a)[2]), "r"((a)[3]), "r"(b0), "r"(b1))

__device__ __forceinline__ void split2(float x, float y, uint32_t& oh, uint32_t& ol) {
    __nv_bfloat16 hx = __float2bfloat16(x), hy = __float2bfloat16(y);
    __nv_bfloat162 th; th.x = hx; th.y = hy;
    __nv_bfloat162 tl;
    tl.x = __float2bfloat16(x - __bfloat162float(hx));
    tl.y = __float2bfloat16(y - __bfloat162float(hy));
    oh = *(uint32_t*)&th; ol = *(uint32_t*)&tl;
}

// ---------------------------------------------------------------------------
// fp32 -> bf16 hi/lo split, all inputs in one launch.
// ---------------------------------------------------------------------------
__global__ __launch_bounds__(256)
void conv_all(const float* __restrict__ x,
              const float* __restrict__ Wq, const float* __restrict__ Wk,
              const float* __restrict__ Wv, const float* __restrict__ Wo)
{
    int blk = blockIdx.x;
    const float* src;
    __nv_bfloat16 *hi, *lo;
    int i;
    if (blk < 4096) {
        src = x; hi = g_xh; lo = g_xl;
        i = blk * 256 + threadIdx.x;
    } else {
        int w  = (blk - 4096) >> 10;
        int bb = (blk - 4096) & 1023;
        src = (w == 0) ? Wq : (w == 1) ? Wk : (w == 2) ? Wv : Wo;
        hi = g_wh + (size_t)w * D_MODEL * D_MODEL;
        lo = g_wl + (size_t)w * D_MODEL * D_MODEL;
        i = bb * 256 + threadIdx.x;
    }

    float4 v = ((const float4*)src)[i];
    uint32_t h01, l01, h23, l23;
    split2(v.x, v.y, h01, l01);
    split2(v.z, v.w, h23, l23);
    ((uint32_t*)hi)[i * 2]     = h01;
    ((uint32_t*)hi)[i * 2 + 1] = h23;
    ((uint32_t*)lo)[i * 2]     = l01;
    ((uint32_t*)lo)[i * 2 + 1] = l23;
}

// ---------------------------------------------------------------------------
// mma.sync bf16-split GEMM: C = A*W^T + bias, 128x128 tile, 8 warps,
// K-chunks of 32, cp.async 3-stage, 1 sync/chunk, 2 CTAs/SM.
// R9: term-major MMA ordering (hh x4nj, hl x4nj, lh x4nj) -> accumulator
//     reuse distance 4 instead of 1.  All acc indices compile-time static.
// ---------------------------------------------------------------------------
#define TILE_B  8192
#define STAGE_B 32768
#define NSTAGE  3
#define SMEM_DYN (NSTAGE * STAGE_B + 1024)

__global__ __launch_bounds__(256, 2)
void gemm_tc(const float* __restrict__ b0, const float* __restrict__ b1,
             const float* __restrict__ b2, float* __restrict__ out_direct, int mode)
{
    extern __shared__ char dsm_raw[];
    char* sm = (char*)(((uintptr_t)dsm_raw + 1023) & ~(uintptr_t)1023);
    const uint32_t sb = smem_u32(sm);
    const int tid = threadIdx.x, wid = tid >> 5, lane = tid & 31;
    const int bn = blockIdx.x * 128, bm = blockIdx.y * 128, z = blockIdx.z;

    const __nv_bfloat16 *Ah, *Al, *Wh, *Wl;
    const float* bias;
    float* C;
    if (mode == 0) {
        Ah = g_xh; Al = g_xl;
        Wh = g_wh + (size_t)z * D_MODEL * D_MODEL;
        Wl = g_wl + (size_t)z * D_MODEL * D_MODEL;
        bias = (z == 0) ? b0 : ((z == 1) ? b1 : b2);
        C = (z == 0) ? g_q : ((z == 1) ? g_k : g_v);
    } else {
        Ah = g_aoh; Al = g_aol;
        Wh = g_wh + (size_t)3 * D_MODEL * D_MODEL;
        Wl = g_wl + (size_t)3 * D_MODEL * D_MODEL;
        bias = b0;
        C = out_direct;
    }

    const int r = tid >> 1;
    const int half = tid & 1;
    const __nv_bfloat16* srcs[4] = {
        Ah + (size_t)(bm + r) * D_MODEL + half * 16,
        Al + (size_t)(bm + r) * D_MODEL + half * 16,
        Wh + (size_t)(bn + r) * D_MODEL + half * 16,
        Wl + (size_t)(bn + r) * D_MODEL + half * 16 };
    uint32_t sts_off[2];
#pragma unroll
    for (int s = 0; s < 2; s++) {
        uint32_t u = (uint32_t)(half * 2 + s);
        sts_off[s] = (uint32_t)r * 64 + ((u ^ ((uint32_t)r & 3)) << 4);
    }

    const int wm = (wid & 1) * 64;
    const int wn = (wid >> 1) * 32;

    float acc[4][4][4];
#pragma unroll
    for (int mi = 0; mi < 4; mi++)
#pragma unroll
        for (int nj = 0; nj < 4; nj++)
#pragma unroll
            for (int q = 0; q < 4; q++) acc[mi][nj][q] = 0.f;

    const uint32_t lrow = lane & 15;
    const uint32_t lsel = lane >> 4;

    // prologue: chunks 0 and 1 -> stages 0 and 1
#pragma unroll
    for (int pc = 0; pc < 2; pc++) {
        uint32_t stb = sb + (uint32_t)pc * STAGE_B;
#pragma unroll
        for (int t = 0; t < 4; t++)
#pragma unroll
            for (int s = 0; s < 2; s++)
                CPA16(stb + t * TILE_B + sts_off[s], srcs[t] + pc * 32 + s * 8);
        CPA_COMMIT();
    }

    int stage_c = 0;
    int stage_n = 2;
    for (int c = 0; c < 32; c++) {
        if (c == 31) { CPA_WAIT0(); } else { CPA_WAIT1(); }
        __syncthreads();

        if (c + 2 < 32) {
            uint32_t stb = sb + (uint32_t)stage_n * STAGE_B;
#pragma unroll
            for (int t = 0; t < 4; t++)
#pragma unroll
                for (int s = 0; s < 2; s++)
                    CPA16(stb + t * TILE_B + sts_off[s], srcs[t] + (c + 2) * 32 + s * 8);
            CPA_COMMIT();
        }

        const uint32_t stg = sb + (uint32_t)stage_c * STAGE_B;
#pragma unroll
        for (int kk = 0; kk < 2; kk++) {
            uint32_t bh[2][4], bl[2][4];
#pragma unroll
            for (int jp = 0; jp < 2; jp++) {
                uint32_t rw = (uint32_t)(wn + jp * 16) + lrow;
                uint32_t u  = ((uint32_t)kk * 2 + lsel) ^ (rw & 3);
                uint32_t ab = stg + rw * 64 + (u << 4);
                LDM4(bh[jp], ab + 2 * TILE_B);
                LDM4(bl[jp], ab + 3 * TILE_B);
            }
#pragma unroll
            for (int mi = 0; mi < 4; mi++) {
                uint32_t ra = (uint32_t)(wm + mi * 16) + lrow;
                uint32_t u  = ((uint32_t)kk * 2 + lsel) ^ (ra & 3);
                uint32_t aa = stg + ra * 64 + (u << 4);
                uint32_t ah[4], al[4];
                LDM4(ah, aa);
                LDM4(al, aa + TILE_B);
                // term-major: 4 independent acc chains per term
#pragma unroll
                for (int nj = 0; nj < 4; nj++) {
                    const int jp = nj >> 1, w = nj & 1;
                    MMA16816(acc[mi][nj], ah, bh[jp][w], bh[jp][w + 2]);
                }
#pragma unroll
                for (int nj = 0; nj < 4; nj++) {
                    const int jp = nj >> 1, w = nj & 1;
                    MMA16816(acc[mi][nj], ah, bl[jp][w], bl[jp][w + 2]);
                }
#pragma unroll
                for (int nj = 0; nj < 4; nj++) {
                    const int jp = nj >> 1, w = nj & 1;
                    MMA16816(acc[mi][nj], al, bh[jp][w], bh[jp][w + 2]);
                }
            }
        }
        stage_c = (stage_c == NSTAGE - 1) ? 0 : stage_c + 1;
        stage_n = (stage_n == NSTAGE - 1) ? 0 : stage_n + 1;
    }

#pragma unroll
    for (int mi = 0; mi < 4; mi++) {
        const int row = bm + wm + mi * 16 + (lane >> 2);
#pragma unroll
        for (int nj = 0; nj < 4; nj++) {
            const int col = bn + wn + nj * 8 + ((lane & 3) << 1);
            float2 o0 = { acc[mi][nj][0] + bias[col], acc[mi][nj][1] + bias[col + 1] };
            float2 o1 = { acc[mi][nj][2] + bias[col], acc[mi][nj][3] + bias[col + 1] };
            *(float2*)&C[(size_t)row * D_MODEL + col]       = o0;
            *(float2*)&C[(size_t)(row + 8) * D_MODEL + col] = o1;
        }
    }
}

// ---------------------------------------------------------------------------
// Tensor-core flash attention with fused RoPE (unchanged from round 7).
// ---------------------------------------------------------------------------
__device__ __forceinline__ void rope16(float* x1, float* x2, int s, int cb, float scale) {
#pragma unroll
    for (int i = 0; i < 16; i++) {
        float invf = exp2f(-(float)(cb + i) * (13.2877123795494f / 32.f));
        float ang = (float)s * invf;
        float sn, cs;
        sincosf(ang, &sn, &cs);
        float o1 = (x1[i] * cs - x2[i] * sn) * scale;
        float o2 = (x1[i] * sn + x2[i] * cs) * scale;
        x1[i] = o1; x2[i] = o2;
    }
}

__device__ __forceinline__ void store_hl(char* bh, char* bl, int row, int cb, const float* v) {
#pragma unroll
    for (int i = 0; i < 16; i += 2) {
        uint32_t off = (uint32_t)row * 128 + (uint32_t)(cb + i) * 2;
        off ^= ((uint32_t)row & 7) << 4;
        uint32_t oh, ol;
        split2(v[i], v[i + 1], oh, ol);
        *(uint32_t*)(bh + off) = oh;
        *(uint32_t*)(bl + off) = ol;
    }
}

__global__ __launch_bounds__(128)
void attn_tc()
{
    __shared__ __align__(16) char sdata[49152];
    char* sQH = sdata;          char* sQL = sdata + 8192;
    char* sKH = sdata + 16384;  char* sKL = sdata + 24576;
    char* sVH = sdata + 32768;  char* sVL = sdata + 40960;
    const uint32_t sb = smem_u32(sdata);

    const int tid = threadIdx.x, wid = tid >> 5, lane = tid & 31;
    const int q0 = blockIdx.x * 64, h = blockIdx.y, b = blockIdx.z;
    const float* Qg = g_q + (size_t)b * SEQ * D_MODEL + h * DH;
    const float* Kg = g_k + (size_t)b * SEQ * D_MODEL + h * DH;
    const float* Vg = g_v + (size_t)b * SEQ * D_MODEL + h * DH;

    const int lrw = tid >> 1;
    const int lch = (tid & 1) * 16;

    {
        const float* qp = Qg + (size_t)(q0 + lrw) * D_MODEL;
        float x1[16], x2[16];
#pragma unroll
        for (int i = 0; i < 16; i += 4) {
            *(float4*)(x1 + i) = *(const float4*)(qp + lch + i);
            *(float4*)(x2 + i) = *(const float4*)(qp + lch + 32 + i);
        }
        rope16(x1, x2, q0 + lrw, lch, 0.125f);
        store_hl(sQH, sQL, lrw, lch, x1);
        store_hl(sQH, sQL, lrw, lch + 32, x2);
    }

    const int wq = wid * 16;
    float m0 = -1e30f, m1 = -1e30f, l0 = 0.f, l1 = 0.f;
    float acc[8][4];
#pragma unroll
    for (int nb = 0; nb < 8; nb++)
#pragma unroll
        for (int q = 0; q < 4; q++) acc[nb][q] = 0.f;

    int kv0 = q0 - WIN; if (kv0 < 0) kv0 = 0;
    const int nk = q0 + 64 - kv0;

    const int qg0 = q0 + wq + (lane >> 2);
    const int qg1 = qg0 + 8;

    for (int kb = 0; kb < nk; kb += 64) {
        const int kbase = kv0 + kb;

        __syncthreads();
        {
            const float* kp = Kg + (size_t)(kbase + lrw) * D_MODEL;
            float x1[16], x2[16];
#pragma unroll
            for (int i = 0; i < 16; i += 4) {
                *(float4*)(x1 + i) = *(const float4*)(kp + lch + i);
                *(float4*)(x2 + i) = *(const float4*)(kp + lch + 32 + i);
            }
            rope16(x1, x2, kbase + lrw, lch, 1.0f);
            store_hl(sKH, sKL, lrw, lch, x1);
            store_hl(sKH, sKL, lrw, lch + 32, x2);

            const float* vp = Vg + (size_t)(kbase + lrw) * D_MODEL;
            const int vc = (tid & 1) * 32;
            float va[16], vb[16];
#pragma unroll
            for (int i = 0; i < 16; i += 4) {
                *(float4*)(va + i) = *(const float4*)(vp + vc + i);
                *(float4*)(vb + i) = *(const float4*)(vp + vc + 16 + i);
            }
            store_hl(sVH, sVL, lrw, vc, va);
            store_hl(sVH, sVL, lrw, vc + 16, vb);
        }
        __syncthreads();

        float S[8][4];
#pragma unroll
        for (int nb = 0; nb < 8; nb++)
#pragma unroll
            for (int q = 0; q < 4; q++) S[nb][q] = 0.f;

#pragma unroll
        for (int ks = 0; ks < 4; ks++) {
            const uint32_t acb  = (uint32_t)ks * 32 + ((uint32_t)(lane >> 4) << 4);
            const uint32_t arow = (uint32_t)wq + (lane & 15);
            const uint32_t aoff = arow * 128 + (acb ^ ((arow & 7) << 4));
            uint32_t ah[4], al[4];
            LDM4(ah, sb + aoff);
            LDM4(al, sb + 8192 + aoff);
#pragma unroll
            for (int nb2 = 0; nb2 < 4; nb2++) {
                const uint32_t brow = (uint32_t)nb2 * 16 + (lane & 15);
                const uint32_t boff = brow * 128 + (acb ^ ((brow & 7) << 4));
                uint32_t bh[4], bl[4];
                LDM4(bh, sb + 16384 + boff);
                LDM4(bl, sb + 24576 + boff);
#pragma unroll
                for (int w = 0; w < 2; w++) {
                    const int nb = nb2 * 2 + w;
                    MMA16816(S[nb], ah, bh[w], bh[w + 2]);
                    MMA16816(S[nb], ah, bl[w], bl[w + 2]);
                    MMA16816(S[nb], al, bh[w], bh[w + 2]);
                }
            }
        }

#pragma unroll
        for (int nb = 0; nb < 8; nb++) {
            const int kg = kbase + nb * 8 + ((lane & 3) << 1);
            if (kg     > qg0 || kg     < qg0 - WIN) S[nb][0] = -1e30f;
            if (kg + 1 > qg0 || kg + 1 < qg0 - WIN) S[nb][1] = -1e30f;
            if (kg     > qg1 || kg     < qg1 - WIN) S[nb][2] = -1e30f;
            if (kg + 1 > qg1 || kg + 1 < qg1 - WIN) S[nb][3] = -1e30f;
        }
        float mx0 = -1e30f, mx1 = -1e30f;
#pragma unroll
        for (int nb = 0; nb < 8; nb++) {
            mx0 = fmaxf(mx0, fmaxf(S[nb][0], S[nb][1]));
            mx1 = fmaxf(mx1, fmaxf(S[nb][2], S[nb][3]));
        }
        mx0 = fmaxf(mx0, __shfl_xor_sync(0xffffffffu, mx0, 1));
        mx0 = fmaxf(mx0, __shfl_xor_sync(0xffffffffu, mx0, 2));
        mx1 = fmaxf(mx1, __shfl_xor_sync(0xffffffffu, mx1, 1));
        mx1 = fmaxf(mx1, __shfl_xor_sync(0xffffffffu, mx1, 2));

        const float mn0 = fmaxf(m0, mx0), mn1 = fmaxf(m1, mx1);
        const float e0 = __expf(m0 - mn0), e1 = __expf(m1 - mn1);
        m0 = mn0; m1 = mn1;

        float s0 = 0.f, s1 = 0.f;
#pragma unroll
        for (int nb = 0; nb < 8; nb++) {
            S[nb][0] = __expf(S[nb][0] - m0); s0 += S[nb][0];
            S[nb][1] = __expf(S[nb][1] - m0); s0 += S[nb][1];
            S[nb][2] = __expf(S[nb][2] - m1); s1 += S[nb][2];
            S[nb][3] = __expf(S[nb][3] - m1); s1 += S[nb][3];
        }
        s0 += __shfl_xor_sync(0xffffffffu, s0, 1);
        s0 += __shfl_xor_sync(0xffffffffu, s0, 2);
        s1 += __shfl_xor_sync(0xffffffffu, s1, 1);
        s1 += __shfl_xor_sync(0xffffffffu, s1, 2);
        l0 = l0 * e0 + s0;
        l1 = l1 * e1 + s1;
#pragma unroll
        for (int nb = 0; nb < 8; nb++) {
            acc[nb][0] *= e0; acc[nb][1] *= e0;
            acc[nb][2] *= e1; acc[nb][3] *= e1;
        }

#pragma unroll
        for (int j = 0; j < 4; j++) {
            uint32_t pah[4], pal[4];
            split2(S[2 * j][0],     S[2 * j][1],     pah[0], pal[0]);
            split2(S[2 * j][2],     S[2 * j][3],     pah[1], pal[1]);
            split2(S[2 * j + 1][0], S[2 * j + 1][1], pah[2], pal[2]);
            split2(S[2 * j + 1][2], S[2 * j + 1][3], pah[3], pal[3]);

            const uint32_t vrow = (uint32_t)j * 16 + (lane & 15);
#pragma unroll
            for (int nb2 = 0; nb2 < 4; nb2++) {
                const uint32_t vcb = (uint32_t)nb2 * 32 + ((uint32_t)(lane >> 4) << 4);
                const uint32_t boff = vrow * 128 + (vcb ^ ((vrow & 7) << 4));
                uint32_t vh[4], vl[4];
                LDM4T(vh, sb + 32768 + boff);
                LDM4T(vl, sb + 40960 + boff);
#pragma unroll
                for (int w = 0; w < 2; w++) {
                    const int nb = nb2 * 2 + w;
                    MMA16816(acc[nb], pah, vh[2 * w], vh[2 * w + 1]);
                    MMA16816(acc[nb], pal, vh[2 * w], vh[2 * w + 1]);
                    MMA16816(acc[nb], pah, vl[2 * w], vl[2 * w + 1]);
                }
            }
        }
    }

    const float inv0 = 1.f / l0, inv1 = 1.f / l1;
#pragma unroll
    for (int nb = 0; nb < 8; nb++) {
        const int col = h * DH + nb * 8 + ((lane & 3) << 1);
        const size_t i0 = ((size_t)b * SEQ + qg0) * D_MODEL + col;
        const size_t i1 = ((size_t)b * SEQ + qg1) * D_MODEL + col;
        uint32_t oh, ol;
        split2(acc[nb][0] * inv0, acc[nb][1] * inv0, oh, ol);
        *(uint32_t*)(g_aoh + i0) = oh;
        *(uint32_t*)(g_aol + i0) = ol;
        split2(acc[nb][2] * inv1, acc[nb][3] * inv1, oh, ol);
        *(uint32_t*)(g_aoh + i1) = oh;
        *(uint32_t*)(g_aol + i1) = ol;
    }
}

// ---------------------------------------------------------------------------
extern "C" void kernel_launch(void* const* d_in, const int* in_sizes, int n_in,
                              void* d_out, int out_size)
{
    const float* x  = (const float*)d_in[0];
    const float* Wq = (const float*)d_in[1];
    const float* bq = (const float*)d_in[2];
    const float* Wk = (const float*)d_in[3];
    const float* bk = (const float*)d_in[4];
    const float* Wv = (const float*)d_in[5];
    const float* bv = (const float*)d_in[6];
    const float* Wo = (const float*)d_in[7];
    const float* bo = (const float*)d_in[8];
    float* out = (float*)d_out;

    cudaFuncSetAttribute(gemm_tc, cudaFuncAttributeMaxDynamicSharedMemorySize, SMEM_DYN);

    conv_all<<<8192, 256>>>(x, Wq, Wk, Wv, Wo);

    gemm_tc<<<dim3(8, 32, 3), 256, SMEM_DYN>>>(bq, bk, bv, nullptr, 0);

    dim3 agrid(SEQ / 64, NHEADS, BATCH);
    attn_tc<<<agrid, 128>>>();

    gemm_tc<<<dim3(8, 32, 1), 256, SMEM_DYN>>>(bo, nullptr, nullptr, out, 1);
}